// round 7
// baseline (speedup 1.0000x reference)
#include <cuda_runtime.h>

#define NP    64                 // patch size
#define CH    4                  // channels
#define PAD   192                // canvas
#define TPB   512
#define PLW   84                 // G plane width (zero borders both sides)
#define PLH   65                 // G rows: iy+1 in [0,64]
#define PLANE (PLW*PLH)          // 5460 floats; multiple of 4
#define SMF   (CH*PLANE)         // 21840 floats = 87,360 B
#define GIN   (63*63)            // interior G positions per channel
#define GBRD  256                // border G positions per channel
#define ZVEC  (CH*PLH*6)         // border zero float4s: 3 left + 3 right per row

// out[b,y,x] = sum_c bilinear(patch_c centered, y-64-dy_c, x-64-dx_c), zero fill.
// Integer pixel coords => bilinear weights constant per (b,c), so
// out(y,x) = G_c[y+oyc][x+oxc], G_c = 2x2 correlation of patch_c with weights.
// G built once per sample in smem; eval reads 8 px/channel via 2 aligned LDS.128.
__global__ __launch_bounds__(TPB, 2)
void reassemble_conv8_kernel(const float* __restrict__ patches,
                             const float* __restrict__ pos,
                             float* __restrict__ out)
{
    extern __shared__ float sm[];        // CH planes of [PLH][PLW]
    const int b   = blockIdx.x;
    const int tid = threadIdx.x;

    // ---- per-channel constants ----
    int   oxc[CH], shf[CH], off0[CH], ylo[CH];
    float w00[CH], w01[CH], w10[CH], w11[CH];
    const float* pb_pos = pos + (size_t)b * 2 * CH;
    #pragma unroll
    for (int c = 0; c < CH; c++) {
        const float dx = __ldg(pb_pos + c);
        const float dy = __ldg(pb_pos + CH + c);
        const float fx = -64.0f - dx;
        const float fy = -64.0f - dy;
        const float flx = floorf(fx), fly = floorf(fy);
        oxc[c] = (int)flx;
        const int oy = (int)fly;
        shf[c] = (4 - (oxc[c] & 3)) & 3;              // (oxc+shf) % 4 == 0
        off0[c] = c * PLANE + (oy + 1) * PLW + oxc[c] + shf[c] + 8;
        ylo[c]  = oy;
        const float wx = fx - flx, wy = fy - fly;
        w00[c] = (1.0f - wx) * (1.0f - wy);
        w01[c] = wx * (1.0f - wy);
        w10[c] = (1.0f - wx) * wy;
        w11[c] = wx * wy;
    }

    // ---- zero border columns: cols [0,11] and [72,83] of every row ----
    {
        float4* smv = reinterpret_cast<float4*>(sm);
        #pragma unroll
        for (int i = tid; i < ZVEC; i += TPB) {        // 1560 vecs -> ~3 iters
            const int plane = i / (PLH * 6);
            const int rem   = i - plane * (PLH * 6);
            const int row   = rem / 6;
            const int v     = rem - row * 6;
            const int col4  = (v < 3) ? (v << 2) : (72 + ((v - 3) << 2));
            smv[(plane * PLANE + row * PLW + col4) >> 2] = make_float4(0.f, 0.f, 0.f, 0.f);
        }
    }
    __syncthreads();

    // ---- build G planes: interior (no tap checks) ----
    const float4* pin = reinterpret_cast<const float4*>(patches + (size_t)b * NP * NP * CH);
    for (int idx = tid; idx < GIN; idx += TPB) {       // ~7.75 iters
        const int r   = idx / 63;                      // 0..62
        const int gxi = idx - r * 63 + 1;              // 1..63
        const int gy  = r + 1;                         // 1..63
        const int ix  = gxi - 1;

        const float4 t00 = __ldg(pin + (gy - 1) * NP + ix);
        const float4 t01 = __ldg(pin + (gy - 1) * NP + ix + 1);
        const float4 t10 = __ldg(pin + gy * NP + ix);
        const float4 t11 = __ldg(pin + gy * NP + ix + 1);

        const int rb = gy * PLW + gxi + 7;
        sm[0 * PLANE + rb + shf[0]] = t00.x * w00[0] + t01.x * w01[0] + t10.x * w10[0] + t11.x * w11[0];
        sm[1 * PLANE + rb + shf[1]] = t00.y * w00[1] + t01.y * w01[1] + t10.y * w10[1] + t11.y * w11[1];
        sm[2 * PLANE + rb + shf[2]] = t00.z * w00[2] + t01.z * w01[2] + t10.z * w10[2] + t11.z * w11[2];
        sm[3 * PLANE + rb + shf[3]] = t00.w * w00[3] + t01.w * w01[3] + t10.w * w10[3] + t11.w * w11[3];
    }

    // ---- build G planes: border positions (checked taps) ----
    if (tid < GBRD) {                                   // 256 positions, 1 iter
        int gy, gxi;
        if (tid < 65)       { gy = 0;         gxi = tid; }
        else if (tid < 130) { gy = 64;        gxi = tid - 65; }
        else if (tid < 193) { gy = tid - 129; gxi = 0;  }   // 1..63
        else                { gy = tid - 192; gxi = 64; }   // 1..63
        const int iy = gy - 1;
        const int ix = gxi - 1;
        const bool r0 = (gy >= 1), r1 = (gy <= 63);
        const bool c0 = (gxi >= 1), c1 = (gxi <= 63);
        const float4 z = make_float4(0.f, 0.f, 0.f, 0.f);
        const float4 t00 = (r0 && c0) ? __ldg(pin + iy * NP + ix)     : z;
        const float4 t01 = (r0 && c1) ? __ldg(pin + iy * NP + ix + 1) : z;
        const float4 t10 = (r1 && c0) ? __ldg(pin + gy * NP + ix)     : z;
        const float4 t11 = (r1 && c1) ? __ldg(pin + gy * NP + ix + 1) : z;

        const int rb = gy * PLW + gxi + 7;
        sm[0 * PLANE + rb + shf[0]] = t00.x * w00[0] + t01.x * w01[0] + t10.x * w10[0] + t11.x * w11[0];
        sm[1 * PLANE + rb + shf[1]] = t00.y * w00[1] + t01.y * w01[1] + t10.y * w10[1] + t11.y * w11[1];
        sm[2 * PLANE + rb + shf[2]] = t00.z * w00[2] + t01.z * w01[2] + t10.z * w10[2] + t11.z * w11[2];
        sm[3 * PLANE + rb + shf[3]] = t00.w * w00[3] + t01.w * w01[3] + t10.w * w10[3] + t11.w * w11[3];
    }
    __syncthreads();

    // ---- eval: 8 consecutive x per thread, 2x LDS.128 + 2x STG.128 ----
    float* ob = out + (size_t)b * PAD * PAD;

    #pragma unroll 3
    for (int q = 0; q < (PAD * PAD / 8) / TPB; q++) {   // 9 iters
        const int g  = q * TPB + tid;                   // 0..4607
        const int y  = g / (PAD / 8);                   // /24
        const int x0 = (g - y * (PAD / 8)) * 8;
        const int pp = y * PLW + x0;

        float a0 = 0.f, a1 = 0.f, a2 = 0.f, a3 = 0.f;
        float a4 = 0.f, a5 = 0.f, a6 = 0.f, a7 = 0.f;

        #pragma unroll
        for (int c = 0; c < CH; c++) {
            const int iy = y + ylo[c];
            if ((unsigned)(iy + 1) > 64u) continue;     // iy outside [-1,63]
            const int ix0 = x0 + oxc[c];
            if ((unsigned)(ix0 + 8) > 71u) continue;    // ix0 outside [-8,63]

            const float* p = sm + off0[c] + pp;
            const float4 gA = *reinterpret_cast<const float4*>(p);
            const float4 gB = *reinterpret_cast<const float4*>(p + 4);
            a0 += gA.x; a1 += gA.y; a2 += gA.z; a3 += gA.w;
            a4 += gB.x; a5 += gB.y; a6 += gB.z; a7 += gB.w;
        }

        float* po = ob + (size_t)y * PAD + x0;
        float4 oA; oA.x = a0; oA.y = a1; oA.z = a2; oA.w = a3;
        float4 oB; oB.x = a4; oB.y = a5; oB.z = a6; oB.w = a7;
        *reinterpret_cast<float4*>(po)     = oA;
        *reinterpret_cast<float4*>(po + 4) = oB;
    }
}

extern "C" void kernel_launch(void* const* d_in, const int* in_sizes, int n_in,
                              void* d_out, int out_size) {
    const float* patches = (const float*)d_in[0];   // (B, 64, 64, 4) fp32
    const float* pos     = (const float*)d_in[1];   // (B, 1, 2, 4)  fp32
    float* out           = (float*)d_out;           // (B, 192, 192, 1) fp32

    const int B = out_size / (PAD * PAD);           // 512
    const int smem_bytes = SMF * sizeof(float);     // 87,360 B
    static bool attr_set = false;
    if (!attr_set) {
        cudaFuncSetAttribute(reassemble_conv8_kernel,
                             cudaFuncAttributeMaxDynamicSharedMemorySize, smem_bytes);
        attr_set = true;
    }
    reassemble_conv8_kernel<<<B, TPB, smem_bytes>>>(patches, pos, out);
}